// round 4
// baseline (speedup 1.0000x reference)
#include <cuda_runtime.h>
#include <math.h>

// QKVAttentionLegacy: qkv (4, 3072, 1024) fp32 -> out (4, 1024, 1024) fp32
// 64 batch-heads, ch=64, T=1024. scale 1/8 on scores (1/sqrt(sqrt(64)) applied to q and k).
//
// Flash-attention, fp32 FMA pipe. CTA = (head, 64-query tile). 256 threads,
// 16x16 thread grid, each thread owns a 4(q) x 4(k or c) fragment.

#define BQ 64
#define BK 64
#define CH 64
#define SEQ 1024
#define NBLK (SEQ / BK)
#define PITCH 68          // pitch (floats) for transposed S and V tiles
#define LOG2E 1.4426950408889634f

// dynamic smem layout (floats):
//   Qs   [CH][64]        : 4096    (Qs[c*64 + q])
//   Ks   [CH][64]        : 4096    (Ks[c*64 + k])
//   Vs   [BK][PITCH]     : 4352    (Vs[k*68 + c])   transposed
//   St   [BK][PITCH]     : 4352    (St[k*68 + q])   transposed scores / P
//   m_run[64] l_run[64] corr[64] redm[64*4] reds[64*4] : 704
// total 17600 floats = 70400 bytes

__global__ void __launch_bounds__(256)
attn_fp32_kernel(const float* __restrict__ qkv, float* __restrict__ out)
{
    extern __shared__ float smem[];
    float* Qs    = smem;                       // 4096
    float* Ks    = Qs + 4096;                  // 4096
    float* Vs    = Ks + 4096;                  // 64*PITCH
    float* St    = Vs + 64 * PITCH;            // 64*PITCH
    float* m_run = St + 64 * PITCH;            // 64
    float* l_run = m_run + 64;                 // 64
    float* corr  = m_run + 128;                // 64
    float* redm  = m_run + 192;                // 256
    float* reds  = m_run + 192 + 256;          // 256

    const int head  = blockIdx.y;              // 0..63  (= b*16 + h)
    const int qtile = blockIdx.x;              // 0..15
    const int tid   = threadIdx.x;
    const int tx    = tid & 15;                // k / c tile coord
    const int ty    = tid >> 4;                // q tile coord

    const float* base = qkv + (size_t)head * 192 * 1024;
    const float* Qg = base;                    // [64][1024]
    const float* Kg = base +  64 * 1024;
    const float* Vg = base + 128 * 1024;

    // ---- load Q tile: Qs[c][q] (same orientation as global) ----
    {
        const int row  = tid >> 2;             // c : 0..63
        const int quad = tid & 3;
        const float4* src = (const float4*)(Qg + row * 1024 + qtile * 64);
        float4* dst = (float4*)(Qs + row * 64);
        #pragma unroll
        for (int j = 0; j < 4; j++)
            dst[quad + 4 * j] = src[quad + 4 * j];
    }
    if (tid < 64) { m_run[tid] = -INFINITY; l_run[tid] = 0.0f; }

    float o[4][4] = {};                        // persistent output fragment

    for (int kb = 0; kb < NBLK; kb++) {
        __syncthreads();  // prev GEMM2 done before overwriting Ks/Vs/St; covers Q load on iter 0

        // ---- load K block (Ks[c][k]) and V block transposed (Vs[k][c]) ----
        {
            const int row  = tid >> 2;         // c
            const int quad = tid & 3;
            const float4* srcK = (const float4*)(Kg + row * 1024 + kb * 64);
            const float4* srcV = (const float4*)(Vg + row * 1024 + kb * 64);
            float4* dstK = (float4*)(Ks + row * 64);
            #pragma unroll
            for (int j = 0; j < 4; j++) {
                dstK[quad + 4 * j] = srcK[quad + 4 * j];
                float4 v = srcV[quad + 4 * j];
                int k0 = (quad + 4 * j) * 4;
                Vs[(k0 + 0) * PITCH + row] = v.x;
                Vs[(k0 + 1) * PITCH + row] = v.y;
                Vs[(k0 + 2) * PITCH + row] = v.z;
                Vs[(k0 + 3) * PITCH + row] = v.w;
            }
        }
        __syncthreads();

        // ---- GEMM1: S[q][k] = sum_c Q[c][q] * K[c][k] ----
        float s[4][4] = {};
        #pragma unroll 8
        for (int c = 0; c < CH; c++) {
            float4 q4 = *(const float4*)(Qs + c * 64 + ty * 4);
            float4 k4 = *(const float4*)(Ks + c * 64 + tx * 4);
            s[0][0] += q4.x * k4.x; s[0][1] += q4.x * k4.y; s[0][2] += q4.x * k4.z; s[0][3] += q4.x * k4.w;
            s[1][0] += q4.y * k4.x; s[1][1] += q4.y * k4.y; s[1][2] += q4.y * k4.z; s[1][3] += q4.y * k4.w;
            s[2][0] += q4.z * k4.x; s[2][1] += q4.z * k4.y; s[2][2] += q4.z * k4.z; s[2][3] += q4.z * k4.w;
            s[3][0] += q4.w * k4.x; s[3][1] += q4.w * k4.y; s[3][2] += q4.w * k4.z; s[3][3] += q4.w * k4.w;
        }
        // write scaled scores transposed: St[k][q]
        #pragma unroll
        for (int j = 0; j < 4; j++) {
            float4 v = make_float4(s[0][j] * 0.125f, s[1][j] * 0.125f,
                                   s[2][j] * 0.125f, s[3][j] * 0.125f);
            *(float4*)(St + (tx * 4 + j) * PITCH + ty * 4) = v;
        }
        __syncthreads();

        // ---- online softmax over this 64-wide block ----
        const int row   = tid >> 2;            // q : 0..63
        const int chunk = tid & 3;             // 16 k's per thread
        // (a) partial max
        float lmax = -INFINITY;
        #pragma unroll
        for (int i = 0; i < 16; i++)
            lmax = fmaxf(lmax, St[(chunk * 16 + i) * PITCH + row]);
        redm[row * 4 + chunk] = lmax;
        __syncthreads();
        // (b) exp + partial sum; update m_run/corr (4 row-threads are in one warp:
        //     the m_run load executes for all lanes before the chunk==0 store)
        float m_old = m_run[row];
        float m_new = fmaxf(m_old,
                       fmaxf(fmaxf(redm[row * 4 + 0], redm[row * 4 + 1]),
                             fmaxf(redm[row * 4 + 2], redm[row * 4 + 3])));
        float psum = 0.0f;
        #pragma unroll
        for (int i = 0; i < 16; i++) {
            int k = chunk * 16 + i;
            float v = St[k * PITCH + row];
            float p = exp2f((v - m_new) * LOG2E);
            St[k * PITCH + row] = p;
            psum += p;
        }
        reds[row * 4 + chunk] = psum;
        if (chunk == 0) {
            corr[row]  = exp2f((m_old - m_new) * LOG2E);  // 0 on first block
            m_run[row] = m_new;
        }
        __syncthreads();
        // (c) update running denom
        if (tid < 64) {
            l_run[tid] = l_run[tid] * corr[tid]
                       + reds[tid * 4 + 0] + reds[tid * 4 + 1]
                       + reds[tid * 4 + 2] + reds[tid * 4 + 3];
        }
        // rescale persistent output fragment
        {
            float c0 = corr[ty * 4 + 0], c1 = corr[ty * 4 + 1];
            float c2 = corr[ty * 4 + 2], c3 = corr[ty * 4 + 3];
            #pragma unroll
            for (int j = 0; j < 4; j++) {
                o[0][j] *= c0; o[1][j] *= c1; o[2][j] *= c2; o[3][j] *= c3;
            }
        }
        // ---- GEMM2: o[q][c] += sum_k P[q][k] * V[c][k] ----
        #pragma unroll 8
        for (int k = 0; k < BK; k++) {
            float4 p4 = *(const float4*)(St + k * PITCH + ty * 4);
            float4 v4 = *(const float4*)(Vs + k * PITCH + tx * 4);
            o[0][0] += p4.x * v4.x; o[0][1] += p4.x * v4.y; o[0][2] += p4.x * v4.z; o[0][3] += p4.x * v4.w;
            o[1][0] += p4.y * v4.x; o[1][1] += p4.y * v4.y; o[1][2] += p4.y * v4.z; o[1][3] += p4.y * v4.w;
            o[2][0] += p4.z * v4.x; o[2][1] += p4.z * v4.y; o[2][2] += p4.z * v4.z; o[2][3] += p4.z * v4.w;
            o[3][0] += p4.w * v4.x; o[3][1] += p4.w * v4.y; o[3][2] += p4.w * v4.z; o[3][3] += p4.w * v4.w;
        }
    }
    __syncthreads();  // final l_run visible to all

    // ---- normalize + write: out[head*65536 + c*1024 + (qtile*64 + q)] ----
    const int q0 = ty * 4;
    float inv0 = 1.0f / l_run[q0 + 0];
    float inv1 = 1.0f / l_run[q0 + 1];
    float inv2 = 1.0f / l_run[q0 + 2];
    float inv3 = 1.0f / l_run[q0 + 3];
    float* obase = out + (size_t)head * 65536 + qtile * 64 + q0;
    #pragma unroll
    for (int j = 0; j < 4; j++) {
        int c = tx * 4 + j;
        float4 v = make_float4(o[0][j] * inv0, o[1][j] * inv1,
                               o[2][j] * inv2, o[3][j] * inv3);
        *(float4*)(obase + c * 1024) = v;
    }
}

extern "C" void kernel_launch(void* const* d_in, const int* in_sizes, int n_in,
                              void* d_out, int out_size)
{
    const float* qkv = (const float*)d_in[0];
    float* out = (float*)d_out;
    (void)in_sizes; (void)n_in; (void)out_size;

    const int smem_bytes = 17600 * 4;  // 70400 B dynamic smem
    cudaFuncSetAttribute(attn_fp32_kernel,
                         cudaFuncAttributeMaxDynamicSharedMemorySize, smem_bytes);

    dim3 grid(NBLK, 64);   // 16 q-tiles x 64 heads
    attn_fp32_kernel<<<grid, 256, smem_bytes>>>(qkv, out);
}

// round 5
// speedup vs baseline: 1.9946x; 1.9946x over previous
#include <cuda_runtime.h>
#include <math.h>

// QKVAttentionLegacy: qkv (4, 3072, 1024) fp32 -> out (4, 1024, 1024) fp32
// 64 heads, ch=64, T=1024, scale 1/8 on scores.
// Flash attention, fp32 FMA pipe. R4: softmax fully in registers (warp shfl),
// stats in registers, P stored row-major (warp-private rows), GEMM2 k-unroll 4.

#define BK 64
#define CH 64
#define SEQ 1024
#define NBLK (SEQ / BK)
#define PITCH 68
// 0.125 * log2(e): scores go straight to log2 domain
#define CSC 0.18033688011112042f

__global__ void __launch_bounds__(256, 3)
attn_fp32_kernel(const float* __restrict__ qkv, float* __restrict__ out)
{
    extern __shared__ float smem[];
    float* Qs = smem;                 // [c][q]  64x64
    float* Ks = Qs + 4096;            // [c][k]  64x64
    float* Vs = Ks + 4096;            // [k][c]  64xPITCH (transposed)
    float* Ss = Vs + 64 * PITCH;      // [q][k]  64xPITCH (P, row-major)

    const int head  = blockIdx.y;     // 0..63
    const int qtile = blockIdx.x;     // 0..15
    const int tid   = threadIdx.x;
    const int tx    = tid & 15;       // k / c fragment coord
    const int ty    = tid >> 4;       // q fragment coord

    const float* base = qkv + (size_t)head * 192 * 1024;
    const float* Qg = base;
    const float* Kg = base +  64 * 1024;
    const float* Vg = base + 128 * 1024;

    // ---- load Q tile: Qs[c][q] ----
    {
        const int row  = tid >> 2;    // c
        const int quad = tid & 3;
        const float4* src = (const float4*)(Qg + row * 1024 + qtile * 64);
        float4* dst = (float4*)(Qs + row * 64);
        #pragma unroll
        for (int j = 0; j < 4; j++)
            dst[quad + 4 * j] = src[quad + 4 * j];
    }

    float m_i[4] = { -INFINITY, -INFINITY, -INFINITY, -INFINITY };
    float l_i[4] = {};
    float o[4][4] = {};

    for (int kb = 0; kb < NBLK; kb++) {
        if (kb) __syncthreads();      // GEMM1/GEMM2 readers done with Ks/Vs

        // ---- load K (Ks[c][k]) and V transposed (Vs[k][c]) ----
        {
            const int row  = tid >> 2;  // c
            const int quad = tid & 3;
            const float4* srcK = (const float4*)(Kg + row * 1024 + kb * 64);
            const float4* srcV = (const float4*)(Vg + row * 1024 + kb * 64);
            float4* dstK = (float4*)(Ks + row * 64);
            #pragma unroll
            for (int j = 0; j < 4; j++) {
                dstK[quad + 4 * j] = srcK[quad + 4 * j];
                float4 v = srcV[quad + 4 * j];
                int k0 = (quad + 4 * j) * 4;
                Vs[(k0 + 0) * PITCH + row] = v.x;
                Vs[(k0 + 1) * PITCH + row] = v.y;
                Vs[(k0 + 2) * PITCH + row] = v.z;
                Vs[(k0 + 3) * PITCH + row] = v.w;
            }
        }
        __syncthreads();              // tiles ready (also covers Q on kb==0)

        // ---- GEMM1: z[q][k] = (sum_c Q[c][q] K[c][k]) * 0.125*log2e ----
        float z[4][4] = {};
        #pragma unroll 8
        for (int c = 0; c < CH; c++) {
            float4 q4 = *(const float4*)(Qs + c * 64 + ty * 4);
            float4 k4 = *(const float4*)(Ks + c * 64 + tx * 4);
            z[0][0] += q4.x * k4.x; z[0][1] += q4.x * k4.y; z[0][2] += q4.x * k4.z; z[0][3] += q4.x * k4.w;
            z[1][0] += q4.y * k4.x; z[1][1] += q4.y * k4.y; z[1][2] += q4.y * k4.z; z[1][3] += q4.y * k4.w;
            z[2][0] += q4.z * k4.x; z[2][1] += q4.z * k4.y; z[2][2] += q4.z * k4.z; z[2][3] += q4.z * k4.w;
            z[3][0] += q4.w * k4.x; z[3][1] += q4.w * k4.y; z[3][2] += q4.w * k4.z; z[3][3] += q4.w * k4.w;
        }
        #pragma unroll
        for (int i = 0; i < 4; i++)
            #pragma unroll
            for (int j = 0; j < 4; j++)
                z[i][j] *= CSC;

        // ---- softmax in registers: reduce over the 16 tx lanes owning each row ----
        float mx[4], rs[4], corr[4];
        #pragma unroll
        for (int i = 0; i < 4; i++)
            mx[i] = fmaxf(fmaxf(z[i][0], z[i][1]), fmaxf(z[i][2], z[i][3]));
        #pragma unroll
        for (int s = 8; s; s >>= 1)
            #pragma unroll
            for (int i = 0; i < 4; i++)
                mx[i] = fmaxf(mx[i], __shfl_xor_sync(0xffffffffu, mx[i], s));

        #pragma unroll
        for (int i = 0; i < 4; i++) {
            float m_new = fmaxf(m_i[i], mx[i]);
            corr[i] = exp2f(m_i[i] - m_new);   // 0 on first block
            m_i[i]  = m_new;
            z[i][0] = exp2f(z[i][0] - m_new);
            z[i][1] = exp2f(z[i][1] - m_new);
            z[i][2] = exp2f(z[i][2] - m_new);
            z[i][3] = exp2f(z[i][3] - m_new);
            rs[i] = (z[i][0] + z[i][1]) + (z[i][2] + z[i][3]);
        }
        #pragma unroll
        for (int s = 8; s; s >>= 1)
            #pragma unroll
            for (int i = 0; i < 4; i++)
                rs[i] += __shfl_xor_sync(0xffffffffu, rs[i], s);
        #pragma unroll
        for (int i = 0; i < 4; i++)
            l_i[i] = l_i[i] * corr[i] + rs[i];

        // ---- store P row-major (warp-private rows), rescale o ----
        #pragma unroll
        for (int i = 0; i < 4; i++) {
            *(float4*)(Ss + (ty * 4 + i) * PITCH + tx * 4) =
                make_float4(z[i][0], z[i][1], z[i][2], z[i][3]);
            o[i][0] *= corr[i]; o[i][1] *= corr[i];
            o[i][2] *= corr[i]; o[i][3] *= corr[i];
        }
        __syncwarp();

        // ---- GEMM2: o[q][c] += sum_k P[q][k] * V[c][k], k unrolled x4 ----
        #pragma unroll 4
        for (int k0 = 0; k0 < BK; k0 += 4) {
            float4 p0 = *(const float4*)(Ss + (ty * 4 + 0) * PITCH + k0);
            float4 p1 = *(const float4*)(Ss + (ty * 4 + 1) * PITCH + k0);
            float4 p2 = *(const float4*)(Ss + (ty * 4 + 2) * PITCH + k0);
            float4 p3 = *(const float4*)(Ss + (ty * 4 + 3) * PITCH + k0);
            float4 v0 = *(const float4*)(Vs + (k0 + 0) * PITCH + tx * 4);
            float4 v1 = *(const float4*)(Vs + (k0 + 1) * PITCH + tx * 4);
            float4 v2 = *(const float4*)(Vs + (k0 + 2) * PITCH + tx * 4);
            float4 v3 = *(const float4*)(Vs + (k0 + 3) * PITCH + tx * 4);

            o[0][0] += p0.x*v0.x + p0.y*v1.x + p0.z*v2.x + p0.w*v3.x;
            o[0][1] += p0.x*v0.y + p0.y*v1.y + p0.z*v2.y + p0.w*v3.y;
            o[0][2] += p0.x*v0.z + p0.y*v1.z + p0.z*v2.z + p0.w*v3.z;
            o[0][3] += p0.x*v0.w + p0.y*v1.w + p0.z*v2.w + p0.w*v3.w;

            o[1][0] += p1.x*v0.x + p1.y*v1.x + p1.z*v2.x + p1.w*v3.x;
            o[1][1] += p1.x*v0.y + p1.y*v1.y + p1.z*v2.y + p1.w*v3.y;
            o[1][2] += p1.x*v0.z + p1.y*v1.z + p1.z*v2.z + p1.w*v3.z;
            o[1][3] += p1.x*v0.w + p1.y*v1.w + p1.z*v2.w + p1.w*v3.w;

            o[2][0] += p2.x*v0.x + p2.y*v1.x + p2.z*v2.x + p2.w*v3.x;
            o[2][1] += p2.x*v0.y + p2.y*v1.y + p2.z*v2.y + p2.w*v3.y;
            o[2][2] += p2.x*v0.z + p2.y*v1.z + p2.z*v2.z + p2.w*v3.z;
            o[2][3] += p2.x*v0.w + p2.y*v1.w + p2.z*v2.w + p2.w*v3.w;

            o[3][0] += p3.x*v0.x + p3.y*v1.x + p3.z*v2.x + p3.w*v3.x;
            o[3][1] += p3.x*v0.y + p3.y*v1.y + p3.z*v2.y + p3.w*v3.y;
            o[3][2] += p3.x*v0.z + p3.y*v1.z + p3.z*v2.z + p3.w*v3.z;
            o[3][3] += p3.x*v0.w + p3.y*v1.w + p3.z*v2.w + p3.w*v3.w;
        }
    }

    // ---- normalize + write: out[head*65536 + c*1024 + (qtile*64 + q)] ----
    float inv0 = 1.0f / l_i[0];
    float inv1 = 1.0f / l_i[1];
    float inv2 = 1.0f / l_i[2];
    float inv3 = 1.0f / l_i[3];
    float* obase = out + (size_t)head * 65536 + qtile * 64 + ty * 4;
    #pragma unroll
    for (int j = 0; j < 4; j++) {
        int c = tx * 4 + j;
        float4 v = make_float4(o[0][j] * inv0, o[1][j] * inv1,
                               o[2][j] * inv2, o[3][j] * inv3);
        *(float4*)(obase + c * 1024) = v;
    }
}

extern "C" void kernel_launch(void* const* d_in, const int* in_sizes, int n_in,
                              void* d_out, int out_size)
{
    const float* qkv = (const float*)d_in[0];
    float* out = (float*)d_out;
    (void)in_sizes; (void)n_in; (void)out_size;

    const int smem_bytes = (4096 + 4096 + 64 * PITCH + 64 * PITCH) * 4;  // 67584 B
    cudaFuncSetAttribute(attn_fp32_kernel,
                         cudaFuncAttributeMaxDynamicSharedMemorySize, smem_bytes);

    dim3 grid(NBLK, 64);
    attn_fp32_kernel<<<grid, 256, smem_bytes>>>(qkv, out);
}

// round 6
// speedup vs baseline: 5.6209x; 2.8180x over previous
#include <cuda_runtime.h>
#include <math.h>
#include <stdint.h>

// QKVAttentionLegacy: qkv (4, 3072, 1024) fp32 -> out (4, 1024, 1024) fp32
// 64 heads, ch=64, T=1024. Flash attention with tf32 mma.sync.m16n8k8.
// CTA = (head, 128-query tile), 256 threads (8 warps), warp w owns q rows [16w,16w+16).

#define SEQ   1024
#define CH    64
#define BQ    128
#define BK    64
#define NBLK  (SEQ / BK)

#define PQ 136   // Qs pitch  (%32==8: A-frag lanes tig*PQ+g -> 8*tig+g distinct)
#define PK 72    // Ks pitch  (%32==8: B-frag lanes tig*PK+g -> 8*tig+g distinct)
#define PV 68    // Vs pitch  (%32==4: B-frag lanes g*PV+tig -> 4*g+tig distinct)
#define PP 68    // Ps pitch  (%32==4: A-frag lanes g*PP+tig -> 4*g+tig distinct)

// sqrt(0.125 * log2(e)) : fold score scale + log2 conversion into Q and K
#define SQK 0.42466087f

__device__ __forceinline__ uint32_t f2tf32(float x) {
    uint32_t u;
    asm("cvt.rna.tf32.f32 %0, %1;" : "=r"(u) : "f"(x));
    return u;
}
__device__ __forceinline__ float ex2(float x) {
    float r;
    asm("ex2.approx.ftz.f32 %0, %1;" : "=f"(r) : "f"(x));
    return r;
}
__device__ __forceinline__ void mma_tf32(float* d,
    uint32_t a0, uint32_t a1, uint32_t a2, uint32_t a3,
    uint32_t b0, uint32_t b1)
{
    asm volatile(
        "mma.sync.aligned.m16n8k8.row.col.f32.tf32.tf32.f32 "
        "{%0,%1,%2,%3}, {%4,%5,%6,%7}, {%8,%9}, {%0,%1,%2,%3};"
        : "+f"(d[0]), "+f"(d[1]), "+f"(d[2]), "+f"(d[3])
        : "r"(a0), "r"(a1), "r"(a2), "r"(a3), "r"(b0), "r"(b1));
}

__global__ void __launch_bounds__(256, 2)
attn_tf32_kernel(const float* __restrict__ qkv, float* __restrict__ out)
{
    extern __shared__ float smem[];
    float* Qs = smem;                    // [c][q] 64 x PQ
    float* Ks = Qs + 64 * PQ;            // [c][k] 64 x PK
    float* Vs = Ks + 64 * PK;            // [c][s] 64 x PV
    float* Ps = Vs + 64 * PV;            // [t][s] 128 x PP

    const int head  = blockIdx.y;        // 0..63
    const int qtile = blockIdx.x;        // 0..7
    const int tid   = threadIdx.x;
    const int lane  = tid & 31;
    const int wid   = tid >> 5;          // 0..7
    const int g     = lane >> 2;         // groupID 0..7
    const int tig   = lane & 3;          // threadInGroup 0..3
    const int qb    = wid * 16;          // warp's q-row base in tile

    const float* base = qkv + (size_t)head * 192 * 1024;
    const float* Qg = base;
    const float* Kg = base +  64 * 1024;
    const float* Vg = base + 128 * 1024;
    const int q0 = qtile * BQ;

    // ---- load Q tile once: Qs[c][q], prescaled, tf32 ----
    for (int i = tid; i < 64 * 32; i += 256) {
        int c = i >> 5, quad = i & 31;
        float4 v = *(const float4*)(Qg + c * 1024 + q0 + quad * 4);
        float4 w;
        w.x = __uint_as_float(f2tf32(v.x * SQK));
        w.y = __uint_as_float(f2tf32(v.y * SQK));
        w.z = __uint_as_float(f2tf32(v.z * SQK));
        w.w = __uint_as_float(f2tf32(v.w * SQK));
        *(float4*)(Qs + c * PQ + quad * 4) = w;
    }

    float o[8][4];
    #pragma unroll
    for (int n = 0; n < 8; n++) { o[n][0]=0.f; o[n][1]=0.f; o[n][2]=0.f; o[n][3]=0.f; }
    float m0 = -INFINITY, m1 = -INFINITY, l0 = 0.f, l1 = 0.f;

    for (int kb = 0; kb < NBLK; kb++) {
        __syncthreads();   // prev GEMM1/2 done with Ks/Vs; also covers Q store on kb==0

        // ---- load K,V blocks: Ks[c][k] (prescaled), Vs[c][s], tf32 ----
        for (int i = tid; i < 64 * 16; i += 256) {
            int c = i >> 4, quad = i & 15;
            float4 k4 = *(const float4*)(Kg + c * 1024 + kb * BK + quad * 4);
            float4 v4 = *(const float4*)(Vg + c * 1024 + kb * BK + quad * 4);
            float4 kw, vw;
            kw.x = __uint_as_float(f2tf32(k4.x * SQK));
            kw.y = __uint_as_float(f2tf32(k4.y * SQK));
            kw.z = __uint_as_float(f2tf32(k4.z * SQK));
            kw.w = __uint_as_float(f2tf32(k4.w * SQK));
            vw.x = __uint_as_float(f2tf32(v4.x));
            vw.y = __uint_as_float(f2tf32(v4.y));
            vw.z = __uint_as_float(f2tf32(v4.z));
            vw.w = __uint_as_float(f2tf32(v4.w));
            *(float4*)(Ks + c * PK + quad * 4) = kw;
            *(float4*)(Vs + c * PV + quad * 4) = vw;
        }
        __syncthreads();

        // ---- GEMM1: z[q,k] = sum_c Q[c,q]*K[c,k]  (already in log2 domain) ----
        float z[8][4];
        #pragma unroll
        for (int n = 0; n < 8; n++) { z[n][0]=0.f; z[n][1]=0.f; z[n][2]=0.f; z[n][3]=0.f; }
        #pragma unroll
        for (int s = 0; s < 8; s++) {
            const float* qa = Qs + (8 * s + tig) * PQ + qb + g;
            uint32_t a0 = __float_as_uint(qa[0]);
            uint32_t a1 = __float_as_uint(qa[8]);
            uint32_t a2 = __float_as_uint(qa[4 * PQ]);
            uint32_t a3 = __float_as_uint(qa[4 * PQ + 8]);
            const float* kr = Ks + (8 * s + tig) * PK + g;
            #pragma unroll
            for (int n = 0; n < 8; n++) {
                uint32_t b0 = __float_as_uint(kr[8 * n]);
                uint32_t b1 = __float_as_uint(kr[4 * PK + 8 * n]);
                mma_tf32(z[n], a0, a1, a2, a3, b0, b1);
            }
        }

        // ---- online softmax (rows r=qb+g and r+8; quad owns cols 2tig,2tig+1 per tile) ----
        float mx0 = -INFINITY, mx1 = -INFINITY;
        #pragma unroll
        for (int n = 0; n < 8; n++) {
            mx0 = fmaxf(mx0, fmaxf(z[n][0], z[n][1]));
            mx1 = fmaxf(mx1, fmaxf(z[n][2], z[n][3]));
        }
        mx0 = fmaxf(mx0, __shfl_xor_sync(0xffffffffu, mx0, 1));
        mx0 = fmaxf(mx0, __shfl_xor_sync(0xffffffffu, mx0, 2));
        mx1 = fmaxf(mx1, __shfl_xor_sync(0xffffffffu, mx1, 1));
        mx1 = fmaxf(mx1, __shfl_xor_sync(0xffffffffu, mx1, 2));

        float m0n = fmaxf(m0, mx0), m1n = fmaxf(m1, mx1);
        float c0 = ex2(m0 - m0n), c1 = ex2(m1 - m1n);  // 0 on first block
        m0 = m0n; m1 = m1n;

        float rs0 = 0.f, rs1 = 0.f;
        #pragma unroll
        for (int n = 0; n < 8; n++) {
            z[n][0] = ex2(z[n][0] - m0n);
            z[n][1] = ex2(z[n][1] - m0n);
            z[n][2] = ex2(z[n][2] - m1n);
            z[n][3] = ex2(z[n][3] - m1n);
            rs0 += z[n][0] + z[n][1];
            rs1 += z[n][2] + z[n][3];
        }
        rs0 += __shfl_xor_sync(0xffffffffu, rs0, 1);
        rs0 += __shfl_xor_sync(0xffffffffu, rs0, 2);
        rs1 += __shfl_xor_sync(0xffffffffu, rs1, 1);
        rs1 += __shfl_xor_sync(0xffffffffu, rs1, 2);
        l0 = l0 * c0 + rs0;
        l1 = l1 * c1 + rs1;

        // rescale o, store P (tf32) to warp-private rows of Ps
        #pragma unroll
        for (int n = 0; n < 8; n++) {
            o[n][0] *= c0; o[n][1] *= c0; o[n][2] *= c1; o[n][3] *= c1;
            uint32_t p0 = f2tf32(z[n][0]), p1 = f2tf32(z[n][1]);
            uint32_t p2 = f2tf32(z[n][2]), p3 = f2tf32(z[n][3]);
            float* pr0 = Ps + (qb + g) * PP + 8 * n + 2 * tig;
            asm volatile("st.shared.v2.b32 [%0], {%1,%2};"
                         :: "l"(__cvta_generic_to_shared(pr0)), "r"(p0), "r"(p1));
            asm volatile("st.shared.v2.b32 [%0], {%1,%2};"
                         :: "l"(__cvta_generic_to_shared(pr0 + 8 * PP)), "r"(p2), "r"(p3));
        }
        __syncwarp();

        // ---- GEMM2: o[t,c] += sum_s P[t,s] * V[c,s] ----
        #pragma unroll
        for (int st = 0; st < 8; st++) {
            const float* pa = Ps + (qb + g) * PP + 8 * st + tig;
            uint32_t a0 = __float_as_uint(pa[0]);
            uint32_t a1 = __float_as_uint(pa[8 * PP]);
            uint32_t a2 = __float_as_uint(pa[4]);
            uint32_t a3 = __float_as_uint(pa[8 * PP + 4]);
            const float* vr = Vs + g * PV + 8 * st + tig;
            #pragma unroll
            for (int n = 0; n < 8; n++) {
                uint32_t b0 = __float_as_uint(vr[8 * n * PV]);
                uint32_t b1 = __float_as_uint(vr[8 * n * PV + 4]);
                mma_tf32(o[n], a0, a1, a2, a3, b0, b1);
            }
        }
    }

    // ---- normalize + store: out[head*65536 + c*1024 + t_global] ----
    float inv0 = 1.0f / l0, inv1 = 1.0f / l1;
    float* ob = out + (size_t)head * 65536 + q0 + qb + g;
    #pragma unroll
    for (int n = 0; n < 8; n++) {
        int col = 8 * n + 2 * tig;
        ob[(size_t)col * 1024]            = o[n][0] * inv0;
        ob[(size_t)(col + 1) * 1024]      = o[n][1] * inv0;
        ob[(size_t)col * 1024 + 8]        = o[n][2] * inv1;
        ob[(size_t)(col + 1) * 1024 + 8]  = o[n][3] * inv1;
    }
}

extern "C" void kernel_launch(void* const* d_in, const int* in_sizes, int n_in,
                              void* d_out, int out_size)
{
    const float* qkv = (const float*)d_in[0];
    float* out = (float*)d_out;
    (void)in_sizes; (void)n_in; (void)out_size;

    const int smem_bytes = (64 * PQ + 64 * PK + 64 * PV + 128 * PP) * 4;  // 105472 B
    cudaFuncSetAttribute(attn_tf32_kernel,
                         cudaFuncAttributeMaxDynamicSharedMemorySize, smem_bytes);

    dim3 grid(SEQ / BQ, 64);   // 8 q-tiles x 64 heads
    attn_tf32_kernel<<<grid, 256, smem_bytes>>>(qkv, out);
}

// round 7
// speedup vs baseline: 6.1789x; 1.0993x over previous
#include <cuda_runtime.h>
#include <math.h>
#include <stdint.h>

// QKVAttentionLegacy: qkv (4, 3072, 1024) fp32 -> out (4, 1024, 1024) fp32
// 64 heads, ch=64, T=1024. Flash attention, tf32 mma.sync.m16n8k8.
// R6: 128-thread CTA, 4 warps, warp owns 32 q rows (two m16 tiles) -> B-frag
// reuse x2 + deeper ILP; K/V register prefetch hides global latency.

#define SEQ   1024
#define CH    64
#define BQ    128
#define BK    64
#define NBLK  (SEQ / BK)

#define PQ 136   // %32==8: GEMM1 A lanes tig*PQ+g conflict-free
#define PK 72    // %32==8: GEMM1 B lanes tig*PK+g conflict-free
#define PV 68    // %32==4: GEMM2 B lanes g*PV+tig conflict-free
#define PP 68    // %32==4: GEMM2 A lanes g*PP+tig conflict-free

// sqrt(0.125 * log2(e)): fold score scale + log2 conversion into Q and K
#define SQK 0.42466087f

__device__ __forceinline__ uint32_t f2tf32(float x) {
    uint32_t u;
    asm("cvt.rna.tf32.f32 %0, %1;" : "=r"(u) : "f"(x));
    return u;
}
__device__ __forceinline__ float ex2(float x) {
    float r;
    asm("ex2.approx.ftz.f32 %0, %1;" : "=f"(r) : "f"(x));
    return r;
}
__device__ __forceinline__ void mma_tf32(float* d,
    uint32_t a0, uint32_t a1, uint32_t a2, uint32_t a3,
    uint32_t b0, uint32_t b1)
{
    asm volatile(
        "mma.sync.aligned.m16n8k8.row.col.f32.tf32.tf32.f32 "
        "{%0,%1,%2,%3}, {%4,%5,%6,%7}, {%8,%9}, {%0,%1,%2,%3};"
        : "+f"(d[0]), "+f"(d[1]), "+f"(d[2]), "+f"(d[3])
        : "r"(a0), "r"(a1), "r"(a2), "r"(a3), "r"(b0), "r"(b1));
}

__global__ void __launch_bounds__(128, 2)
attn_tf32_kernel(const float* __restrict__ qkv, float* __restrict__ out)
{
    extern __shared__ float smem[];
    float* Qs = smem;                    // [c][q]  64 x PQ
    float* Ks = Qs + 64 * PQ;            // [c][k]  64 x PK
    float* Vs = Ks + 64 * PK;            // [c][s]  64 x PV
    float* Ps = Vs + 64 * PV;            // [t][s] 128 x PP

    const int head  = blockIdx.y;        // 0..63
    const int qtile = blockIdx.x;        // 0..7
    const int tid   = threadIdx.x;       // 0..127
    const int lane  = tid & 31;
    const int wid   = tid >> 5;          // 0..3
    const int g     = lane >> 2;         // 0..7
    const int tig   = lane & 3;          // 0..3
    const int qb    = wid * 32;          // warp's q-row base (two m16 tiles)

    const float* base = qkv + (size_t)head * 192 * 1024;
    const float* Qg = base;
    const float* Kg = base +  64 * 1024;
    const float* Vg = base + 128 * 1024;
    const int q0 = qtile * BQ;

    // ---- load Q tile once: Qs[c][q], prescaled, tf32 ----
    for (int i = tid; i < 64 * 32; i += 128) {
        int c = i >> 5, quad = i & 31;
        float4 v = *(const float4*)(Qg + c * 1024 + q0 + quad * 4);
        float4 w;
        w.x = __uint_as_float(f2tf32(v.x * SQK));
        w.y = __uint_as_float(f2tf32(v.y * SQK));
        w.z = __uint_as_float(f2tf32(v.z * SQK));
        w.w = __uint_as_float(f2tf32(v.w * SQK));
        *(float4*)(Qs + c * PQ + quad * 4) = w;
    }

    float o[2][8][4];
    #pragma unroll
    for (int mm = 0; mm < 2; mm++)
        #pragma unroll
        for (int n = 0; n < 8; n++)
            { o[mm][n][0]=0.f; o[mm][n][1]=0.f; o[mm][n][2]=0.f; o[mm][n][3]=0.f; }
    float m_i[2][2] = {{-INFINITY,-INFINITY},{-INFINITY,-INFINITY}};
    float l_i[2][2] = {{0.f,0.f},{0.f,0.f}};

    // ---- prefetch K/V block 0 into registers ----
    float4 kpf[8], vpf[8];
    #pragma unroll
    for (int j = 0; j < 8; j++) {
        int i = tid + 128 * j, c = i >> 4, quad = i & 15;
        kpf[j] = *(const float4*)(Kg + c * 1024 + quad * 4);
        vpf[j] = *(const float4*)(Vg + c * 1024 + quad * 4);
    }

    for (int kb = 0; kb < NBLK; kb++) {
        __syncthreads();   // prior readers done with Ks/Vs/Ps (covers Q store on kb==0)

        // ---- commit prefetched K/V to smem (convert to tf32, K prescaled) ----
        #pragma unroll
        for (int j = 0; j < 8; j++) {
            int i = tid + 128 * j, c = i >> 4, quad = i & 15;
            float4 kw, vw;
            kw.x = __uint_as_float(f2tf32(kpf[j].x * SQK));
            kw.y = __uint_as_float(f2tf32(kpf[j].y * SQK));
            kw.z = __uint_as_float(f2tf32(kpf[j].z * SQK));
            kw.w = __uint_as_float(f2tf32(kpf[j].w * SQK));
            vw.x = __uint_as_float(f2tf32(vpf[j].x));
            vw.y = __uint_as_float(f2tf32(vpf[j].y));
            vw.z = __uint_as_float(f2tf32(vpf[j].z));
            vw.w = __uint_as_float(f2tf32(vpf[j].w));
            *(float4*)(Ks + c * PK + quad * 4) = kw;
            *(float4*)(Vs + c * PV + quad * 4) = vw;
        }
        __syncthreads();

        // ---- prefetch next block's K (overlaps GEMM1) ----
        if (kb + 1 < NBLK) {
            #pragma unroll
            for (int j = 0; j < 8; j++) {
                int i = tid + 128 * j, c = i >> 4, quad = i & 15;
                kpf[j] = *(const float4*)(Kg + c * 1024 + (kb + 1) * BK + quad * 4);
            }
        }

        // ---- GEMM1: z[m][q,k] = sum_c Q[c,q] K[c,k] (log2 domain) ----
        float z[2][8][4];
        #pragma unroll
        for (int mm = 0; mm < 2; mm++)
            #pragma unroll
            for (int n = 0; n < 8; n++)
                { z[mm][n][0]=0.f; z[mm][n][1]=0.f; z[mm][n][2]=0.f; z[mm][n][3]=0.f; }
        #pragma unroll
        for (int s = 0; s < 8; s++) {
            const float* qa = Qs + (8 * s + tig) * PQ + qb + g;
            uint32_t a00 = __float_as_uint(qa[0]);
            uint32_t a01 = __float_as_uint(qa[8]);
            uint32_t a02 = __float_as_uint(qa[4 * PQ]);
            uint32_t a03 = __float_as_uint(qa[4 * PQ + 8]);
            uint32_t a10 = __float_as_uint(qa[16]);
            uint32_t a11 = __float_as_uint(qa[24]);
            uint32_t a12 = __float_as_uint(qa[4 * PQ + 16]);
            uint32_t a13 = __float_as_uint(qa[4 * PQ + 24]);
            const float* krow = Ks + (8 * s + tig) * PK + g;
            #pragma unroll
            for (int n = 0; n < 8; n++) {
                uint32_t b0 = __float_as_uint(krow[8 * n]);
                uint32_t b1 = __float_as_uint(krow[4 * PK + 8 * n]);
                mma_tf32(z[0][n], a00, a01, a02, a03, b0, b1);
                mma_tf32(z[1][n], a10, a11, a12, a13, b0, b1);
            }
        }

        // ---- online softmax per m-tile (rows g and g+8; cols 2tig,2tig+1) ----
        float corr[2][2];
        #pragma unroll
        for (int mm = 0; mm < 2; mm++) {
            float mx0 = -INFINITY, mx1 = -INFINITY;
            #pragma unroll
            for (int n = 0; n < 8; n++) {
                mx0 = fmaxf(mx0, fmaxf(z[mm][n][0], z[mm][n][1]));
                mx1 = fmaxf(mx1, fmaxf(z[mm][n][2], z[mm][n][3]));
            }
            mx0 = fmaxf(mx0, __shfl_xor_sync(0xffffffffu, mx0, 1));
            mx0 = fmaxf(mx0, __shfl_xor_sync(0xffffffffu, mx0, 2));
            mx1 = fmaxf(mx1, __shfl_xor_sync(0xffffffffu, mx1, 1));
            mx1 = fmaxf(mx1, __shfl_xor_sync(0xffffffffu, mx1, 2));

            float m0n = fmaxf(m_i[mm][0], mx0);
            float m1n = fmaxf(m_i[mm][1], mx1);
            corr[mm][0] = ex2(m_i[mm][0] - m0n);   // 0 on first block
            corr[mm][1] = ex2(m_i[mm][1] - m1n);
            m_i[mm][0] = m0n; m_i[mm][1] = m1n;

            float rs0 = 0.f, rs1 = 0.f;
            #pragma unroll
            for (int n = 0; n < 8; n++) {
                z[mm][n][0] = ex2(z[mm][n][0] - m0n);
                z[mm][n][1] = ex2(z[mm][n][1] - m0n);
                z[mm][n][2] = ex2(z[mm][n][2] - m1n);
                z[mm][n][3] = ex2(z[mm][n][3] - m1n);
                rs0 += z[mm][n][0] + z[mm][n][1];
                rs1 += z[mm][n][2] + z[mm][n][3];
            }
            rs0 += __shfl_xor_sync(0xffffffffu, rs0, 1);
            rs0 += __shfl_xor_sync(0xffffffffu, rs0, 2);
            rs1 += __shfl_xor_sync(0xffffffffu, rs1, 1);
            rs1 += __shfl_xor_sync(0xffffffffu, rs1, 2);
            l_i[mm][0] = l_i[mm][0] * corr[mm][0] + rs0;
            l_i[mm][1] = l_i[mm][1] * corr[mm][1] + rs1;
        }

        // ---- prefetch next block's V (overlaps P-store + GEMM2) ----
        if (kb + 1 < NBLK) {
            #pragma unroll
            for (int j = 0; j < 8; j++) {
                int i = tid + 128 * j, c = i >> 4, quad = i & 15;
                vpf[j] = *(const float4*)(Vg + c * 1024 + (kb + 1) * BK + quad * 4);
            }
        }

        // ---- store P (tf32) to warp-private rows; rescale o ----
        #pragma unroll
        for (int mm = 0; mm < 2; mm++) {
            float* prow = Ps + (qb + 16 * mm + g) * PP + 2 * tig;
            #pragma unroll
            for (int n = 0; n < 8; n++) {
                o[mm][n][0] *= corr[mm][0]; o[mm][n][1] *= corr[mm][0];
                o[mm][n][2] *= corr[mm][1]; o[mm][n][3] *= corr[mm][1];
                uint32_t p0 = f2tf32(z[mm][n][0]), p1 = f2tf32(z[mm][n][1]);
                uint32_t p2 = f2tf32(z[mm][n][2]), p3 = f2tf32(z[mm][n][3]);
                asm volatile("st.shared.v2.b32 [%0], {%1,%2};"
                    :: "l"(__cvta_generic_to_shared(prow + 8 * n)), "r"(p0), "r"(p1));
                asm volatile("st.shared.v2.b32 [%0], {%1,%2};"
                    :: "l"(__cvta_generic_to_shared(prow + 8 * PP + 8 * n)), "r"(p2), "r"(p3));
            }
        }
        __syncwarp();

        // ---- GEMM2: o[m][t,c] += sum_s P[t,s] V[c,s] ----
        #pragma unroll
        for (int st = 0; st < 8; st++) {
            const float* pa0 = Ps + (qb + g) * PP + 8 * st + tig;
            const float* pa1 = pa0 + 16 * PP;
            uint32_t a00 = __float_as_uint(pa0[0]);
            uint32_t a01 = __float_as_uint(pa0[8 * PP]);
            uint32_t a02 = __float_as_uint(pa0[4]);
            uint32_t a03 = __float_as_uint(pa0[8 * PP + 4]);
            uint32_t a10 = __float_as_uint(pa1[0]);
            uint32_t a11 = __float_as_uint(pa1[8 * PP]);
            uint32_t a12 = __float_as_uint(pa1[4]);
            uint32_t a13 = __float_as_uint(pa1[8 * PP + 4]);
            const float* vrow = Vs + g * PV + 8 * st + tig;
            #pragma unroll
            for (int n = 0; n < 8; n++) {
                uint32_t b0 = __float_as_uint(vrow[8 * n * PV]);
                uint32_t b1 = __float_as_uint(vrow[8 * n * PV + 4]);
                mma_tf32(o[0][n], a00, a01, a02, a03, b0, b1);
                mma_tf32(o[1][n], a10, a11, a12, a13, b0, b1);
            }
        }
    }

    // ---- normalize + store: out[head*65536 + c*1024 + t_global] ----
    #pragma unroll
    for (int mm = 0; mm < 2; mm++) {
        float inv0 = 1.0f / l_i[mm][0];
        float inv1 = 1.0f / l_i[mm][1];
        float* ob = out + (size_t)head * 65536 + q0 + qb + 16 * mm + g;
        #pragma unroll
        for (int n = 0; n < 8; n++) {
            int col = 8 * n + 2 * tig;
            ob[(size_t)col * 1024]           = o[mm][n][0] * inv0;
            ob[(size_t)(col + 1) * 1024]     = o[mm][n][1] * inv0;
            ob[(size_t)col * 1024 + 8]       = o[mm][n][2] * inv1;
            ob[(size_t)(col + 1) * 1024 + 8] = o[mm][n][3] * inv1;
        }
    }
}

extern "C" void kernel_launch(void* const* d_in, const int* in_sizes, int n_in,
                              void* d_out, int out_size)
{
    const float* qkv = (const float*)d_in[0];
    float* out = (float*)d_out;
    (void)in_sizes; (void)n_in; (void)out_size;

    const int smem_bytes = (64 * PQ + 64 * PK + 64 * PV + 128 * PP) * 4;  // 105472 B
    cudaFuncSetAttribute(attn_tf32_kernel,
                         cudaFuncAttributeMaxDynamicSharedMemorySize, smem_bytes);

    dim3 grid(SEQ / BQ, 64);   // 8 q-tiles x 64 heads = 512 CTAs
    attn_tf32_kernel<<<grid, 128, smem_bytes>>>(qkv, out);
}

// round 8
// speedup vs baseline: 6.9356x; 1.1225x over previous
#include <cuda_runtime.h>
#include <math.h>
#include <stdint.h>

// QKVAttentionLegacy: qkv (4, 3072, 1024) fp32 -> out (4, 1024, 1024) fp32
// 64 heads, ch=64, T=1024. Flash attention, tf32 mma.sync.m16n8k8.
// R7: Q fragments persistent in registers (A-side LDS eliminated),
//     K/V double-buffered in smem via cp.async (raw fp32, RNA->tf32 cvt in regs),
//     128-thread CTA, warp owns 32 q rows (two m16 tiles).

#define SEQ   1024
#define BQ    128
#define BK    64
#define NBLK  (SEQ / BK)

#define PK 72    // %32==8: GEMM1 B lanes conflict-free
#define PV 68    // %32==4: GEMM2 B lanes conflict-free
#define PP 68    // %32==4: GEMM2 A lanes conflict-free

// float offsets in dynamic smem
#define OFF_K0 0
#define OFF_K1 (64 * PK)
#define OFF_V0 (2 * 64 * PK)
#define OFF_V1 (2 * 64 * PK + 64 * PV)
#define OFF_P  (2 * 64 * PK + 2 * 64 * PV)
#define SMEM_FLOATS (OFF_P + 128 * PP)          // 26624 floats = 106496 B

// 0.125 * log2(e): whole score scale folded into Q
#define SC 0.18033688011112042f

__device__ __forceinline__ uint32_t f2tf32(float x) {
    uint32_t u;
    asm("cvt.rna.tf32.f32 %0, %1;" : "=r"(u) : "f"(x));
    return u;
}
__device__ __forceinline__ float ex2(float x) {
    float r;
    asm("ex2.approx.ftz.f32 %0, %1;" : "=f"(r) : "f"(x));
    return r;
}
__device__ __forceinline__ void mma_tf32(float* d,
    uint32_t a0, uint32_t a1, uint32_t a2, uint32_t a3,
    uint32_t b0, uint32_t b1)
{
    asm volatile(
        "mma.sync.aligned.m16n8k8.row.col.f32.tf32.tf32.f32 "
        "{%0,%1,%2,%3}, {%4,%5,%6,%7}, {%8,%9}, {%0,%1,%2,%3};"
        : "+f"(d[0]), "+f"(d[1]), "+f"(d[2]), "+f"(d[3])
        : "r"(a0), "r"(a1), "r"(a2), "r"(a3), "r"(b0), "r"(b1));
}
__device__ __forceinline__ void cp16(uint32_t saddr, const void* gptr) {
    asm volatile("cp.async.cg.shared.global [%0], [%1], 16;"
                 :: "r"(saddr), "l"(gptr));
}

__global__ void __launch_bounds__(128, 2)
attn_tf32_kernel(const float* __restrict__ qkv, float* __restrict__ out)
{
    extern __shared__ float smem[];
    float* Ps = smem + OFF_P;

    const int head  = blockIdx.y;        // 0..63
    const int qtile = blockIdx.x;        // 0..7
    const int tid   = threadIdx.x;       // 0..127
    const int lane  = tid & 31;
    const int wid   = tid >> 5;          // 0..3
    const int g     = lane >> 2;         // 0..7
    const int tig   = lane & 3;          // 0..3
    const int qb    = wid * 32;          // warp's q-row base (two m16 tiles)

    const float* base = qkv + (size_t)head * 192 * 1024;
    const float* Qg = base;
    const float* Kg = base +  64 * 1024;
    const float* Vg = base + 128 * 1024;
    const int q0 = qtile * BQ;

    const uint32_t smem_u32 = (uint32_t)__cvta_generic_to_shared(smem);
    const uint32_t ku32[2] = { smem_u32 + OFF_K0 * 4u, smem_u32 + OFF_K1 * 4u };
    const uint32_t vu32[2] = { smem_u32 + OFF_V0 * 4u, smem_u32 + OFF_V1 * 4u };

    // ---- issue cp.async for K/V block 0 ----
    {
        #pragma unroll
        for (int j = 0; j < 8; j++) {
            int i = tid + 128 * j, c = i >> 4, quad = i & 15;
            cp16(ku32[0] + (c * PK + quad * 4) * 4u, Kg + c * 1024 + quad * 4);
            cp16(vu32[0] + (c * PV + quad * 4) * 4u, Vg + c * 1024 + quad * 4);
        }
        asm volatile("cp.async.commit_group;");
    }

    // ---- Q fragments, loop-invariant (scaled by SC, tf32 RNA) ----
    uint32_t qA[8][2][4];
    {
        const float* qc = Qg + q0 + qb + g;
        #pragma unroll
        for (int s = 0; s < 8; s++) {
            int c0 = 8 * s + tig;
            #pragma unroll
            for (int mm = 0; mm < 2; mm++) {
                int col = 16 * mm;
                qA[s][mm][0] = f2tf32(qc[(size_t)c0 * 1024 + col] * SC);
                qA[s][mm][1] = f2tf32(qc[(size_t)c0 * 1024 + col + 8] * SC);
                qA[s][mm][2] = f2tf32(qc[(size_t)(c0 + 4) * 1024 + col] * SC);
                qA[s][mm][3] = f2tf32(qc[(size_t)(c0 + 4) * 1024 + col + 8] * SC);
            }
        }
    }

    float o[2][8][4];
    #pragma unroll
    for (int mm = 0; mm < 2; mm++)
        #pragma unroll
        for (int n = 0; n < 8; n++)
            { o[mm][n][0]=0.f; o[mm][n][1]=0.f; o[mm][n][2]=0.f; o[mm][n][3]=0.f; }
    float m_i[2][2] = {{-INFINITY,-INFINITY},{-INFINITY,-INFINITY}};
    float l_i[2][2] = {{0.f,0.f},{0.f,0.f}};

    for (int kb = 0; kb < NBLK; kb++) {
        const int b = kb & 1;
        const float* ksb = smem + (b ? OFF_K1 : OFF_K0);
        const float* vsb = smem + (b ? OFF_V1 : OFF_V0);

        __syncthreads();    // all warps done reading buf b^1 (previous compute)

        if (kb + 1 < NBLK) {
            const float* Kn = Kg + (kb + 1) * BK;
            const float* Vn = Vg + (kb + 1) * BK;
            #pragma unroll
            for (int j = 0; j < 8; j++) {
                int i = tid + 128 * j, c = i >> 4, quad = i & 15;
                cp16(ku32[b ^ 1] + (c * PK + quad * 4) * 4u, Kn + c * 1024 + quad * 4);
                cp16(vu32[b ^ 1] + (c * PV + quad * 4) * 4u, Vn + c * 1024 + quad * 4);
            }
        }
        asm volatile("cp.async.commit_group;");
        asm volatile("cp.async.wait_group 1;");   // block kb's copies (this thread) done
        __syncthreads();                          // everyone's copies done

        // ---- GEMM1: z = Q^T K (log2 domain; K cvt'd in regs) ----
        float z[2][8][4];
        #pragma unroll
        for (int mm = 0; mm < 2; mm++)
            #pragma unroll
            for (int n = 0; n < 8; n++)
                { z[mm][n][0]=0.f; z[mm][n][1]=0.f; z[mm][n][2]=0.f; z[mm][n][3]=0.f; }
        #pragma unroll
        for (int s = 0; s < 8; s++) {
            const float* kr = ksb + (8 * s + tig) * PK + g;
            #pragma unroll
            for (int n = 0; n < 8; n++) {
                uint32_t b0 = f2tf32(kr[8 * n]);
                uint32_t b1 = f2tf32(kr[4 * PK + 8 * n]);
                mma_tf32(z[0][n], qA[s][0][0], qA[s][0][1], qA[s][0][2], qA[s][0][3], b0, b1);
                mma_tf32(z[1][n], qA[s][1][0], qA[s][1][1], qA[s][1][2], qA[s][1][3], b0, b1);
            }
        }

        // ---- online softmax per m-tile ----
        float corr[2][2];
        #pragma unroll
        for (int mm = 0; mm < 2; mm++) {
            float mx0 = -INFINITY, mx1 = -INFINITY;
            #pragma unroll
            for (int n = 0; n < 8; n++) {
                mx0 = fmaxf(mx0, fmaxf(z[mm][n][0], z[mm][n][1]));
                mx1 = fmaxf(mx1, fmaxf(z[mm][n][2], z[mm][n][3]));
            }
            mx0 = fmaxf(mx0, __shfl_xor_sync(0xffffffffu, mx0, 1));
            mx0 = fmaxf(mx0, __shfl_xor_sync(0xffffffffu, mx0, 2));
            mx1 = fmaxf(mx1, __shfl_xor_sync(0xffffffffu, mx1, 1));
            mx1 = fmaxf(mx1, __shfl_xor_sync(0xffffffffu, mx1, 2));

            float m0n = fmaxf(m_i[mm][0], mx0);
            float m1n = fmaxf(m_i[mm][1], mx1);
            corr[mm][0] = ex2(m_i[mm][0] - m0n);   // 0 on first block
            corr[mm][1] = ex2(m_i[mm][1] - m1n);
            m_i[mm][0] = m0n; m_i[mm][1] = m1n;

            float rs0 = 0.f, rs1 = 0.f;
            #pragma unroll
            for (int n = 0; n < 8; n++) {
                z[mm][n][0] = ex2(z[mm][n][0] - m0n);
                z[mm][n][1] = ex2(z[mm][n][1] - m0n);
                z[mm][n][2] = ex2(z[mm][n][2] - m1n);
                z[mm][n][3] = ex2(z[mm][n][3] - m1n);
                rs0 += z[mm][n][0] + z[mm][n][1];
                rs1 += z[mm][n][2] + z[mm][n][3];
            }
            rs0 += __shfl_xor_sync(0xffffffffu, rs0, 1);
            rs0 += __shfl_xor_sync(0xffffffffu, rs0, 2);
            rs1 += __shfl_xor_sync(0xffffffffu, rs1, 1);
            rs1 += __shfl_xor_sync(0xffffffffu, rs1, 2);
            l_i[mm][0] = l_i[mm][0] * corr[mm][0] + rs0;
            l_i[mm][1] = l_i[mm][1] * corr[mm][1] + rs1;
        }

        // ---- store P (tf32) to warp-private rows; rescale o ----
        #pragma unroll
        for (int mm = 0; mm < 2; mm++) {
            float* prow = Ps + (qb + 16 * mm + g) * PP + 2 * tig;
            #pragma unroll
            for (int n = 0; n < 8; n++) {
                o[mm][n][0] *= corr[mm][0]; o[mm][n][1] *= corr[mm][0];
                o[mm][n][2] *= corr[mm][1]; o[mm][n][3] *= corr[mm][1];
                uint32_t p0 = f2tf32(z[mm][n][0]), p1 = f2tf32(z[mm][n][1]);
                uint32_t p2 = f2tf32(z[mm][n][2]), p3 = f2tf32(z[mm][n][3]);
                asm volatile("st.shared.v2.b32 [%0], {%1,%2};"
                    :: "l"(__cvta_generic_to_shared(prow + 8 * n)), "r"(p0), "r"(p1));
                asm volatile("st.shared.v2.b32 [%0], {%1,%2};"
                    :: "l"(__cvta_generic_to_shared(prow + 8 * PP + 8 * n)), "r"(p2), "r"(p3));
            }
        }
        __syncwarp();

        // ---- GEMM2: o += P V^T (V cvt'd in regs) ----
        #pragma unroll
        for (int st = 0; st < 8; st++) {
            const float* pa0 = Ps + (qb + g) * PP + 8 * st + tig;
            const float* pa1 = pa0 + 16 * PP;
            uint32_t a00 = __float_as_uint(pa0[0]);
            uint32_t a01 = __float_as_uint(pa0[8 * PP]);
            uint32_t a02 = __float_as_uint(pa0[4]);
            uint32_t a03 = __float_as_uint(pa0[8 * PP + 4]);
            uint32_t a10 = __float_as_uint(pa1[0]);
            uint32_t a11 = __float_as_uint(pa1[8 * PP]);
            uint32_t a12 = __float_as_uint(pa1[4]);
            uint32_t a13 = __float_as_uint(pa1[8 * PP + 4]);
            const float* vr = vsb + g * PV + 8 * st + tig;
            #pragma unroll
            for (int n = 0; n < 8; n++) {
                uint32_t b0 = f2tf32(vr[8 * n * PV]);
                uint32_t b1 = f2tf32(vr[8 * n * PV + 4]);
                mma_tf32(o[0][n], a00, a01, a02, a03, b0, b1);
                mma_tf32(o[1][n], a10, a11, a12, a13, b0, b1);
            }
        }
    }

    // ---- normalize + store: out[head*65536 + c*1024 + t_global] ----
    #pragma unroll
    for (int mm = 0; mm < 2; mm++) {
        float inv0 = 1.0f / l_i[mm][0];
        float inv1 = 1.0f / l_i[mm][1];
        float* ob = out + (size_t)head * 65536 + q0 + qb + 16 * mm + g;
        #pragma unroll
        for (int n = 0; n < 8; n++) {
            int col = 8 * n + 2 * tig;
            ob[(size_t)col * 1024]           = o[mm][n][0] * inv0;
            ob[(size_t)(col + 1) * 1024]     = o[mm][n][1] * inv0;
            ob[(size_t)col * 1024 + 8]       = o[mm][n][2] * inv1;
            ob[(size_t)(col + 1) * 1024 + 8] = o[mm][n][3] * inv1;
        }
    }
}

extern "C" void kernel_launch(void* const* d_in, const int* in_sizes, int n_in,
                              void* d_out, int out_size)
{
    const float* qkv = (const float*)d_in[0];
    float* out = (float*)d_out;
    (void)in_sizes; (void)n_in; (void)out_size;

    const int smem_bytes = SMEM_FLOATS * 4;   // 106496 B
    cudaFuncSetAttribute(attn_tf32_kernel,
                         cudaFuncAttributeMaxDynamicSharedMemorySize, smem_bytes);

    dim3 grid(SEQ / BQ, 64);   // 8 q-tiles x 64 heads = 512 CTAs
    attn_tf32_kernel<<<grid, 128, smem_bytes>>>(qkv, out);
}